// round 9
// baseline (speedup 1.0000x reference)
#include <cuda_runtime.h>
#include <cuda_bf16.h>
#include <math.h>

// ---------- election hash table: 2^21 slots x 8B = 16MB ----------
// word = (cell+1) << 23 | (pair+1) << 3 | bucket ; 0 = empty.
// Within a cell, word order == pair order -> max = last pair wins.
// Zeroed by se_sweep_bin each call -> replay-deterministic.
#define TBL_BITS 21
#define TBL_SIZE (1u << TBL_BITS)
#define TBL_MASK (TBL_SIZE - 1u)
__device__ unsigned long long g_tbl[TBL_SIZE];

// ---------- per-region winner lists ----------
// region = cell >> 14 (64KB of output each). 4096 regions, cap 512
// (mean ~128 winners/region, uniform -> cap is >30 sigma).
#define N_REG   4096
#define REG_CAP 512
#define REG_FLOATS 16384            // floats per region (64KB)
__device__ uint2 g_rwin[N_REG * REG_CAP];   // (offset_in_region, float_bits)
__device__ int   g_rcnt[N_REG];             // zeroed by fill kernel each call

// Pass 1: blind-first-CAS election (1 atomic for the common case).
__global__ void se_elect(const int* __restrict__ src,
                         const int* __restrict__ dst,
                         const int* __restrict__ path_len,
                         int n_pairs, int nn, int max_path) {
    int i = blockIdx.x * blockDim.x + threadIdx.x;
    if (i >= n_pairs) return;

    int s  = __ldg(&src[i]);
    int d  = __ldg(&dst[i]);
    int pl = __ldg(&path_len[i]);
    int bu = (pl < max_path ? pl : max_path) - 1;
    if (bu < 0) bu = 0;

    unsigned cell = (unsigned)s * (unsigned)nn + (unsigned)d;
    unsigned long long cid  = (unsigned long long)(cell + 1u);
    unsigned long long mine = (cid << 23) |
                              ((unsigned long long)(unsigned)(i + 1) << 3) |
                              (unsigned long long)bu;

    unsigned h = (cell * 2654435761u) & TBL_MASK;
    unsigned long long expected = 0ull;
    for (;;) {
        unsigned long long old = atomicCAS(&g_tbl[h], expected, mine);
        if (old == expected) break;              // installed
        if ((old >> 23) == cid) {                // my cell owns this slot
            if (old >= mine) break;              // later pair already won
            expected = old;                      // retry same slot
        } else {                                 // other cell: next slot
            h = (h + 1u) & TBL_MASK;
            expected = 0ull;
        }
    }
}

// Pass 2: stream table, zero it, bin winners by 64KB output region.
__global__ void se_sweep_bin(const float* __restrict__ b) {
    unsigned t = blockIdx.x * blockDim.x + threadIdx.x;   // one ull2 / thread
    ulonglong2* p = reinterpret_cast<ulonglong2*>(g_tbl) + t;
    ulonglong2 w = *p;
    if (w.x | w.y) {
        *p = make_ulonglong2(0ull, 0ull);                 // self-clean
        #pragma unroll
        for (int k = 0; k < 2; k++) {
            unsigned long long word = k ? w.y : w.x;
            if (!word) continue;
            unsigned cell = (unsigned)(word >> 23) - 1u;
            unsigned reg  = cell >> 14;
            unsigned off  = cell & (REG_FLOATS - 1u);
            unsigned vb   = __float_as_uint(__ldg(&b[(unsigned)word & 7u]));
            int slot = atomicAdd(&g_rcnt[reg], 1);
            if (slot < REG_CAP)
                g_rwin[reg * REG_CAP + slot] = make_uint2(off, vb);
        }
    }
}

// Pass 3: fused fill + scatter. Each block zeroes its contiguous 64KB region
// with 16 independent STG.128 per thread, then scatters its winners into the
// lines it just dirtied (L2 hits). Resets its region counter for next replay.
__global__ void __launch_bounds__(256)
se_fill_scatter(float4* __restrict__ out4, int n_floats) {
    int reg = blockIdx.x;
    int tid = threadIdx.x;
    float4* base4 = out4 + (size_t)reg * (REG_FLOATS / 4);
    long long rem = (long long)n_floats - (long long)reg * REG_FLOATS;
    if (rem <= 0) return;

    float4 z = make_float4(0.f, 0.f, 0.f, 0.f);
    if (rem >= REG_FLOATS) {
        #pragma unroll
        for (int j = 0; j < REG_FLOATS / 4 / 256; j++)
            base4[j * 256 + tid] = z;
    } else {
        int n4 = (int)(rem >> 2);
        for (int j = tid; j < n4; j += 256) base4[j] = z;
    }
    __syncthreads();   // zeros ordered before winner stores (CTA-wide)

    int cnt = g_rcnt[reg];
    if (cnt > REG_CAP) cnt = REG_CAP;
    float* basef = reinterpret_cast<float*>(base4);
    const uint2* wl = &g_rwin[reg * REG_CAP];
    for (int i = tid; i < cnt; i += 256) {
        uint2 e = wl[i];
        basef[e.x] = __uint_as_float(e.y);
    }
    if (tid == 0) g_rcnt[reg] = 0;   // self-clean for next replay
}

extern "C" void kernel_launch(void* const* d_in, const int* in_sizes, int n_in,
                              void* d_out, int out_size) {
    // inputs: x [n_nodes,128] f32 (unused), b [max_path] f32,
    //         src [n_pairs] i32, dst [n_pairs] i32, path_len [n_pairs] i32
    const float* b        = (const float*)d_in[1];
    const int*   src      = (const int*)d_in[2];
    const int*   dst      = (const int*)d_in[3];
    const int*   path_len = (const int*)d_in[4];

    int max_path = in_sizes[1];
    int n_pairs  = in_sizes[2];
    int nn = (int)(sqrt((double)out_size) + 0.5);

    const int T = 256;

    // 1) election (16MB L2-resident hash table, blind-first CAS)
    int blocksA = (n_pairs + T - 1) / T;
    se_elect<<<blocksA, T>>>(src, dst, path_len, n_pairs, nn, max_path);

    // 2) sweep table -> per-region winner lists (table self-cleans)
    int blocksB = (TBL_SIZE / 2 + T - 1) / T;
    se_sweep_bin<<<blocksB, T>>>(b);

    // 3) fused zero-fill + winner scatter (one block per 64KB region)
    int n_regions = (out_size + REG_FLOATS - 1) / REG_FLOATS;
    se_fill_scatter<<<n_regions, T>>>((float4*)d_out, out_size);
}

// round 10
// speedup vs baseline: 1.1529x; 1.1529x over previous
#include <cuda_runtime.h>
#include <cuda_bf16.h>
#include <math.h>

// Election hash table: 2^21 slots x 8B = 16MB, L2-resident in steady state
// (the sweep re-dirties exactly these lines every replay).
// word = (cell+1) << 23 | (pair+1) << 3 | bucket ; 0 = empty.
// Same-cell threads deterministically converge on one slot (probe advances
// only past words owned by OTHER cells; ownership never changes).
// Zeroed by se_sweep each call -> replay-deterministic.
#define TBL_BITS 21
#define TBL_SIZE (1u << TBL_BITS)
#define TBL_MASK (TBL_SIZE - 1u)
__device__ unsigned long long g_tbl[TBL_SIZE];

#define PPT 4   // pairs per thread (int4-vectorized input loads)

__device__ __forceinline__ void elect_one(unsigned cell, int i, int bu) {
    unsigned long long cid  = (unsigned long long)(cell + 1u);
    unsigned long long mine = (cid << 23) |
                              ((unsigned long long)(unsigned)(i + 1) << 3) |
                              (unsigned long long)bu;
    unsigned h = (cell * 2654435761u) & TBL_MASK;
    unsigned long long expected = 0ull;
    for (;;) {
        unsigned long long old = atomicCAS(&g_tbl[h], expected, mine);
        if (old == expected) break;              // installed
        if ((old >> 23) == cid) {                // my cell owns this slot
            if (old >= mine) break;              // later pair already won
            expected = old;                      // retry same slot
        } else {                                 // other cell: next slot
            h = (h + 1u) & TBL_MASK;
            expected = 0ull;
        }
    }
}

// Pass A: election. int4 loads -> 3 coalesced loads per 4 pairs + 1 CAS/pair.
// Runs CONCURRENTLY with the CE memset: touches only g_tbl (L2) + 6MB inputs.
__global__ void se_elect(const int4* __restrict__ src4,
                         const int4* __restrict__ dst4,
                         const int4* __restrict__ path_len4,
                         int n_quads, int n_pairs, int nn, int max_path) {
    int q = blockIdx.x * blockDim.x + threadIdx.x;
    if (q >= n_quads) return;

    int4 s4 = __ldg(&src4[q]);
    int4 d4 = __ldg(&dst4[q]);
    int4 p4 = __ldg(&path_len4[q]);

    int i0 = q * 4;
    int sv[4] = {s4.x, s4.y, s4.z, s4.w};
    int dv[4] = {d4.x, d4.y, d4.z, d4.w};
    int pv[4] = {p4.x, p4.y, p4.z, p4.w};

#pragma unroll
    for (int k = 0; k < 4; k++) {
        int i = i0 + k;
        if (i >= n_pairs) break;
        int bu = (pv[k] < max_path ? pv[k] : max_path) - 1;
        if (bu < 0) bu = 0;
        unsigned cell = (unsigned)sv[k] * (unsigned)nn + (unsigned)dv[k];
        elect_one(cell, i, bu);
    }
}

// Pass B: vectorized sweep of the (L2-hot) table. Nonzero slots write their
// winner value to out (the single cold-random pass) and self-clean.
__global__ void se_sweep(const float* __restrict__ b,
                         float* __restrict__ out_f) {
    unsigned t = blockIdx.x * blockDim.x + threadIdx.x;   // one ull2 / thread
    ulonglong2* p = reinterpret_cast<ulonglong2*>(g_tbl) + t;
    ulonglong2 w = *p;
    if (w.x | w.y) {
        *p = make_ulonglong2(0ull, 0ull);                 // self-clean
        if (w.x) {
            unsigned cell = (unsigned)(w.x >> 23) - 1u;
            out_f[cell] = __ldg(&b[(unsigned)w.x & 7u]);
        }
        if (w.y) {
            unsigned cell = (unsigned)(w.y >> 23) - 1u;
            out_f[cell] = __ldg(&b[(unsigned)w.y & 7u]);
        }
    }
}

extern "C" void kernel_launch(void* const* d_in, const int* in_sizes, int n_in,
                              void* d_out, int out_size) {
    // inputs: x [n_nodes,128] f32 (unused), b [max_path] f32,
    //         src [n_pairs] i32, dst [n_pairs] i32, path_len [n_pairs] i32
    const float* b        = (const float*)d_in[1];
    const int*   src      = (const int*)d_in[2];
    const int*   dst      = (const int*)d_in[3];
    const int*   path_len = (const int*)d_in[4];

    int max_path = in_sizes[1];
    int n_pairs  = in_sizes[2];
    int nn = (int)(sqrt((double)out_size) + 0.5);

    // One-time side stream + events for the capture fork (host objects only).
    static cudaStream_t s2 = nullptr;
    static cudaEvent_t evFork = nullptr, evJoin = nullptr;
    if (s2 == nullptr) {
        cudaStreamCreateWithFlags(&s2, cudaStreamNonBlocking);
        cudaEventCreateWithFlags(&evFork, cudaEventDisableTiming);
        cudaEventCreateWithFlags(&evJoin, cudaEventDisableTiming);
    }

    const int T = 256;
    int n_quads = (n_pairs + 3) / 4;
    int blocksA = (n_quads + T - 1) / T;

    // Fork: elect (L2-resident table, minimal DRAM) overlaps the CE memset
    // (pure DRAM stream into d_out). Disjoint resources, disjoint buffers.
    cudaEventRecord(evFork, 0);
    cudaStreamWaitEvent(s2, evFork, 0);

    se_elect<<<blocksA, T, 0, s2>>>((const int4*)src, (const int4*)dst,
                                    (const int4*)path_len,
                                    n_quads, n_pairs, nn, max_path);

    cudaMemsetAsync(d_out, 0, (size_t)out_size * sizeof(float), 0);

    // Join: sweep needs BOTH the zeroed out and the finished election.
    cudaEventRecord(evJoin, s2);
    cudaStreamWaitEvent(0, evJoin, 0);

    int blocksB = (TBL_SIZE / 2 + T - 1) / T;
    se_sweep<<<blocksB, T>>>(b, (float*)d_out);
}